// round 11
// baseline (speedup 1.0000x reference)
#include <cuda_runtime.h>
#include <cuda_bf16.h>
#include <math.h>
#include <stdint.h>

// ---------------------------------------------------------------------------
// Problem constants
// ---------------------------------------------------------------------------
#define BD   2
#define CD   768
#define HD   12
#define DD   64
#define NX   16384
#define NM   4096
#define GRID_H 16
#define GRID_W 256
#define EPSF 1e-6f
#define KVSPLIT 16

#define MQ (NX * BD)   // 32768
#define MK (NM * BD)   // 8192

// ---------------------------------------------------------------------------
// Scratch (__device__ globals; no cudaMalloc allowed)
// ---------------------------------------------------------------------------
__device__ float g_q  [(size_t)MQ * CD];
__device__ float g_k  [(size_t)MK * CD];
__device__ float g_v  [(size_t)MK * CD];
__device__ float g_dwc[(size_t)MK * CD];
__device__ float g_kvp[(size_t)KVSPLIT * BD * HD * DD * DD];
__device__ float g_kmp[(size_t)KVSPLIT * BD * HD * DD];
__device__ float g_kv [(size_t)BD * HD * DD * DD];
__device__ float g_km [(size_t)BD * HD * DD];
__device__ float g_rsp[CD];                      // 1/softplus(scale)

// bf16 split-pair buffers
__device__ __nv_bfloat16 g_ah[(size_t)MQ * CD];  // x hi (reused for attn output hi)
__device__ __nv_bfloat16 g_al[(size_t)MQ * CD];  // x lo (reused for attn output lo)
__device__ __nv_bfloat16 g_bh[(size_t)MK * CD];  // memory hi
__device__ __nv_bfloat16 g_bl[(size_t)MK * CD];  // memory lo
__device__ __nv_bfloat16 g_wh[4 * CD * CD];      // wq, wk, wv, wproj hi (contiguous)
__device__ __nv_bfloat16 g_wl[4 * CD * CD];      // lo

// ---------------------------------------------------------------------------
// PTX helpers (family-safe: mma.sync + cp.async + ldmatrix)
// ---------------------------------------------------------------------------
__device__ __forceinline__ uint32_t smem_u32(const void* p) {
    uint32_t a;
    asm("{ .reg .u64 t; cvta.to.shared.u64 t, %1; cvt.u32.u64 %0, t; }"
        : "=r"(a) : "l"(p));
    return a;
}

// NOTE: .ca is load-bearing — .cg regressed the GEMM 315->509us on sm_103a (round 8).
// NOTE: 2-stage + STR40 padding is the proven-fast config; 3-stage swizzle
//       regressed 316->332us (round 10). Do not "improve" this mainloop again
//       without per-kernel profile evidence.
#define CP_ASYNC16(dst, src) \
    asm volatile("cp.async.ca.shared.global [%0], [%1], 16;" :: "r"(dst), "l"(src))
#define CP_COMMIT() asm volatile("cp.async.commit_group;")
#define CP_WAIT1()  asm volatile("cp.async.wait_group 1;")
#define CP_WAIT0()  asm volatile("cp.async.wait_group 0;")

#define MMA_BF16(c, a, b) \
    asm volatile( \
        "mma.sync.aligned.m16n8k16.row.col.f32.bf16.bf16.f32 " \
        "{%0,%1,%2,%3}, {%4,%5,%6,%7}, {%8,%9}, {%0,%1,%2,%3};" \
        : "+f"((c)[0]), "+f"((c)[1]), "+f"((c)[2]), "+f"((c)[3]) \
        : "r"((a)[0]), "r"((a)[1]), "r"((a)[2]), "r"((a)[3]), \
          "r"((b)[0]), "r"((b)[1]))

#define LDSM4(r, addr) \
    asm volatile("ldmatrix.sync.aligned.m8n8.x4.shared.b16 {%0,%1,%2,%3}, [%4];" \
        : "=r"((r)[0]), "=r"((r)[1]), "=r"((r)[2]), "=r"((r)[3]) : "r"(addr))

// ---------------------------------------------------------------------------
// HMMA split-bf16 GEMM (round-9 config): C[M,N'] = (Ah+Al)*(Wh+Wl)^T
// CTA tile 128x128, BK=32, 8 warps (4m x 2n), 2 stages, STR=40 padding,
// 2 CTAs/SM. Dual-output epilogue for merged K/V GEMM.
// ---------------------------------------------------------------------------
#define STR     40
#define TILE_B  (128 * STR * 2)          // 10240 bytes
#define STAGE_B (4 * TILE_B)             // 40960
#define GEMM_SMEM (2 * STAGE_B)          // 81920
#define NCHUNK  (CD / 32)                // 24

template<bool BIAS>
__global__ __launch_bounds__(256, 2)
void gemm_mma(const __nv_bfloat16* __restrict__ Ah, const __nv_bfloat16* __restrict__ Al,
              const __nv_bfloat16* __restrict__ Wh, const __nv_bfloat16* __restrict__ Wl,
              float* __restrict__ C0, float* __restrict__ C1,
              const float* __restrict__ bias)
{
    extern __shared__ char smem[];
    const uint32_t sb = smem_u32(smem);
    const int tid  = threadIdx.x;
    const int wid  = tid >> 5;
    const int lane = tid & 31;
    const int n0 = blockIdx.x * 128;
    const int m0 = blockIdx.y * 128;

    const int moff = (wid & 3) * 32;
    const int noff = (wid >> 2) * 64;
    const int gid  = lane >> 2;
    const int qid  = lane & 3;

    const int lq = lane >> 3;
    const int lr = lane & 7;
    const int a_row = (lq & 1) * 8 + lr;
    const int a_kc  = (lq >> 1) * 8;
    const int b_row = (lq >> 1) * 8 + lr;
    const int b_kc  = (lq & 1) * 8;

    const __nv_bfloat16* srcs[4] = { Ah, Al, Wh, Wl };
    const int brow[4] = { m0, m0, n0, n0 };

    auto load_chunk = [&](int kc, int st) {
#pragma unroll
        for (int t = 0; t < 4; t++) {
            const __nv_bfloat16* src = srcs[t];
#pragma unroll
            for (int i = 0; i < 2; i++) {
                int idx = tid + i * 256;
                int row = idx >> 2;
                int seg = idx & 3;
                const __nv_bfloat16* g = src + (size_t)(brow[t] + row) * CD + kc + seg * 8;
                uint32_t d = sb + st * STAGE_B + t * TILE_B + (row * STR + seg * 8) * 2;
                CP_ASYNC16(d, g);
            }
        }
        CP_COMMIT();
    };

    float acc[2][8][4];
#pragma unroll
    for (int mt = 0; mt < 2; mt++)
#pragma unroll
        for (int nt = 0; nt < 8; nt++)
#pragma unroll
            for (int j = 0; j < 4; j++) acc[mt][nt][j] = 0.f;

    load_chunk(0, 0);
    load_chunk(32, 1);

    for (int c = 0; c < NCHUNK; c++) {
        if (c < NCHUNK - 1) { CP_WAIT1(); } else { CP_WAIT0(); }
        __syncthreads();

        const int st = c & 1;
        const uint32_t sAh = sb + st * STAGE_B + 0 * TILE_B;
        const uint32_t sAl = sb + st * STAGE_B + 1 * TILE_B;
        const uint32_t sWh = sb + st * STAGE_B + 2 * TILE_B;
        const uint32_t sWl = sb + st * STAGE_B + 3 * TILE_B;

#pragma unroll
        for (int ks = 0; ks < 2; ks++) {
            const int kb = ks * 16;

            uint32_t a[2][4], al2[2][4];
#pragma unroll
            for (int mt = 0; mt < 2; mt++) {
                uint32_t ra = ((moff + mt * 16 + a_row) * STR + kb + a_kc) * 2;
                LDSM4(a[mt],   sAh + ra);
                LDSM4(al2[mt], sAl + ra);
            }

            uint32_t bh[4][4], bl[4][4];
#pragma unroll
            for (int p = 0; p < 4; p++) {
                uint32_t rb = ((noff + p * 16 + b_row) * STR + kb + b_kc) * 2;
                LDSM4(bh[p], sWh + rb);
                LDSM4(bl[p], sWl + rb);
            }

#pragma unroll
            for (int mt = 0; mt < 2; mt++)
#pragma unroll
                for (int nt = 0; nt < 8; nt++) {
                    MMA_BF16(acc[mt][nt], a[mt],   &bh[nt >> 1][(nt & 1) * 2]);
                    MMA_BF16(acc[mt][nt], a[mt],   &bl[nt >> 1][(nt & 1) * 2]);
                    MMA_BF16(acc[mt][nt], al2[mt], &bh[nt >> 1][(nt & 1) * 2]);
                }
        }

        __syncthreads();
        if (c + 2 < NCHUNK) load_chunk((c + 2) * 32, st);
    }

    // ---- epilogue: route to C0 (cols < 768) or C1 (cols >= 768) ----
    float* Cb = C0;
    int nb = n0;
    if (n0 >= CD) { Cb = C1; nb = n0 - CD; }

#pragma unroll
    for (int mt = 0; mt < 2; mt++) {
        int r0 = m0 + moff + mt * 16 + gid;
#pragma unroll
        for (int nt = 0; nt < 8; nt++) {
            int col = nb + noff + nt * 8 + qid * 2;
            float b0 = 0.f, b1 = 0.f;
            if (BIAS) { b0 = __ldg(bias + col); b1 = __ldg(bias + col + 1); }
            float2 v0 = make_float2(acc[mt][nt][0] + b0, acc[mt][nt][1] + b1);
            float2 v1 = make_float2(acc[mt][nt][2] + b0, acc[mt][nt][3] + b1);
            *(float2*)(Cb + (size_t)r0 * CD + col)       = v0;
            *(float2*)(Cb + (size_t)(r0 + 8) * CD + col) = v1;
        }
    }
}

// ---------------------------------------------------------------------------
// fp32 -> (bf16 hi, bf16 lo) split conversion
// ---------------------------------------------------------------------------
__global__ void cvt_pair(const float4* __restrict__ src,
                         __nv_bfloat162* __restrict__ hi,
                         __nv_bfloat162* __restrict__ lo, int n4)
{
    int i = blockIdx.x * blockDim.x + threadIdx.x;
    if (i >= n4) return;
    float4 v = src[i];
    __nv_bfloat16 h0 = __float2bfloat16(v.x), h1 = __float2bfloat16(v.y);
    __nv_bfloat16 h2 = __float2bfloat16(v.z), h3 = __float2bfloat16(v.w);
    __nv_bfloat16 l0 = __float2bfloat16(v.x - __bfloat162float(h0));
    __nv_bfloat16 l1 = __float2bfloat16(v.y - __bfloat162float(h1));
    __nv_bfloat16 l2 = __float2bfloat16(v.z - __bfloat162float(h2));
    __nv_bfloat16 l3 = __float2bfloat16(v.w - __bfloat162float(h3));
    hi[2 * i]     = __halves2bfloat162(h0, h1);
    hi[2 * i + 1] = __halves2bfloat162(h2, h3);
    lo[2 * i]     = __halves2bfloat162(l0, l1);
    lo[2 * i + 1] = __halves2bfloat162(l2, l3);
}

// merged conversion of all 4 weight matrices (blockIdx.y selects tensor)
__global__ void cvt_weights(const float4* __restrict__ w0, const float4* __restrict__ w1,
                            const float4* __restrict__ w2, const float4* __restrict__ w3,
                            __nv_bfloat162* __restrict__ hi, __nv_bfloat162* __restrict__ lo)
{
    const int n4 = CD * CD / 4;
    int i = blockIdx.x * blockDim.x + threadIdx.x;
    if (i >= n4) return;
    const float4* src = (blockIdx.y == 0) ? w0 : (blockIdx.y == 1) ? w1
                      : (blockIdx.y == 2) ? w2 : w3;
    size_t o = (size_t)blockIdx.y * (CD * CD / 2);
    float4 v = src[i];
    __nv_bfloat16 h0 = __float2bfloat16(v.x), h1 = __float2bfloat16(v.y);
    __nv_bfloat16 h2 = __float2bfloat16(v.z), h3 = __float2bfloat16(v.w);
    __nv_bfloat16 l0 = __float2bfloat16(v.x - __bfloat162float(h0));
    __nv_bfloat16 l1 = __float2bfloat16(v.y - __bfloat162float(h1));
    __nv_bfloat16 l2 = __float2bfloat16(v.z - __bfloat162float(h2));
    __nv_bfloat16 l3 = __float2bfloat16(v.w - __bfloat162float(h3));
    hi[o + 2 * i]     = __halves2bfloat162(h0, h1);
    hi[o + 2 * i + 1] = __halves2bfloat162(h2, h3);
    lo[o + 2 * i]     = __halves2bfloat162(l0, l1);
    lo[o + 2 * i + 1] = __halves2bfloat162(l2, l3);
}

// ---------------------------------------------------------------------------
// 1/softplus(scale)
// ---------------------------------------------------------------------------
__global__ void rsoftplus_kernel(const float* __restrict__ scale, float* __restrict__ rsp)
{
    int c = blockIdx.x * blockDim.x + threadIdx.x;
    if (c < CD) {
        float s = scale[c];
        float sp = (s > 20.f) ? s : log1pf(expf(s));
        rsp[c] = 1.f / sp;
    }
}

// ---------------------------------------------------------------------------
// Focusing nonlinearity for k (in-place)
// ---------------------------------------------------------------------------
__global__ __launch_bounds__(256) void process_kernel(float* __restrict__ t,
                                                      const float* __restrict__ rsp)
{
    float* row = t + (size_t)blockIdx.x * CD;
    const int tid = threadIdx.x;

    float v[3];
    float s2 = 0.f, s6 = 0.f;
#pragma unroll
    for (int i = 0; i < 3; i++) {
        int c = tid + i * 256;
        float x = row[c];
        x = (x > 0.f ? x : 0.f) + EPSF;
        x = x * rsp[c];
        v[i] = x;
        float x2 = x * x;
        s2 += x2;
        s6 += x2 * x2 * x2;
    }
#pragma unroll
    for (int off = 16; off > 0; off >>= 1) {
        s2 += __shfl_xor_sync(0xffffffffu, s2, off);
        s6 += __shfl_xor_sync(0xffffffffu, s6, off);
    }
    __shared__ float sA[8], sB[8];
    int warp = tid >> 5, lane = tid & 31;
    if (lane == 0) { sA[warp] = s2; sB[warp] = s6; }
    __syncthreads();
    if (warp == 0) {
        float a = (lane < 8) ? sA[lane] : 0.f;
        float b = (lane < 8) ? sB[lane] : 0.f;
#pragma unroll
        for (int off = 4; off > 0; off >>= 1) {
            a += __shfl_xor_sync(0xffffffffu, a, off);
            b += __shfl_xor_sync(0xffffffffu, b, off);
        }
        if (lane == 0) { sA[0] = a; sB[0] = b; }
    }
    __syncthreads();
    float f = sqrtf(sA[0]) / sqrtf(sB[0]);
#pragma unroll
    for (int i = 0; i < 3; i++) {
        int c = tid + i * 256;
        row[c] = v[i] * v[i] * v[i] * f;
    }
}

// ---------------------------------------------------------------------------
// kv partial + reduce
// ---------------------------------------------------------------------------
__global__ __launch_bounds__(256) void kv_partial_kernel(const float* __restrict__ k,
                                                         const float* __restrict__ v,
                                                         float* __restrict__ kvp,
                                                         float* __restrict__ kmp)
{
    const int bh = blockIdx.x;
    const int b  = bh / HD;
    const int hh = bh % HD;
    const int n0 = blockIdx.y * (NM / KVSPLIT);
    const int t  = threadIdx.x;
    const int d1 = t >> 2;
    const int c0 = (t & 3) * 16;

    __shared__ float ks[DD], vs[DD];

    float acc[16];
#pragma unroll
    for (int j = 0; j < 16; j++) acc[j] = 0.f;
    float ksum = 0.f;

    for (int n = n0; n < n0 + NM / KVSPLIT; n++) {
        size_t base = ((size_t)n * BD + b) * CD + hh * DD;
        if (t < DD)           ks[t]      = k[base + t];
        else if (t < 2 * DD)  vs[t - DD] = v[base + t - DD];
        __syncthreads();
        float kd = ks[d1];
#pragma unroll
        for (int j = 0; j < 16; j++) acc[j] = fmaf(kd, vs[c0 + j], acc[j]);
        if (t < DD) ksum += ks[t];
        __syncthreads();
    }

    const float s = 1.f / (float)NM;
    float* outp = kvp + ((size_t)blockIdx.y * (BD * HD) + bh) * (DD * DD) + d1 * DD + c0;
#pragma unroll
    for (int j = 0; j < 16; j++) outp[j] = acc[j] * s;
    if (t < DD) kmp[((size_t)blockIdx.y * (BD * HD) + bh) * DD + t] = ksum * s;
}

__global__ void kv_reduce_kernel(const float* __restrict__ kvp, const float* __restrict__ kmp,
                                 float* __restrict__ kv, float* __restrict__ km)
{
    int idx = blockIdx.x * blockDim.x + threadIdx.x;
    const int NKV = BD * HD * DD * DD;
    const int NKM = BD * HD * DD;
    if (idx < NKV) {
        float s = 0.f;
#pragma unroll
        for (int p = 0; p < KVSPLIT; p++) s += kvp[(size_t)p * NKV + idx];
        kv[idx] = s;
    } else if (idx < NKV + NKM) {
        int i = idx - NKV;
        float s = 0.f;
#pragma unroll
        for (int p = 0; p < KVSPLIT; p++) s += kmp[(size_t)p * NKM + i];
        km[i] = s;
    }
}

// ---------------------------------------------------------------------------
// depthwise 5x5 conv (bias included)
// ---------------------------------------------------------------------------
__global__ __launch_bounds__(256) void dwconv_kernel(const float* __restrict__ v,
                                                     const float* __restrict__ w,
                                                     const float* __restrict__ bias,
                                                     float* __restrict__ dwc)
{
    __shared__ float ws[DD * 25];
    __shared__ float bs[DD];
    const int t = threadIdx.x;
    for (int i = t; i < DD * 25; i += 256) ws[i] = w[i];
    if (t < DD) bs[t] = bias[t];
    __syncthreads();

    size_t idx = (size_t)blockIdx.x * 256 + t;
    int c  = (int)(idx % CD);
    int rb = (int)(idx / CD);
    int b  = rb & 1;
    int n  = rb >> 1;
    int y   = n >> 8;
    int col = n & 255;
    int dd  = c & (DD - 1);

    float acc = bs[dd];
#pragma unroll
    for (int dy = -2; dy <= 2; dy++) {
        int y2 = y + dy;
        if (y2 < 0 || y2 >= GRID_H) continue;
#pragma unroll
        for (int dx = -2; dx <= 2; dx++) {
            int c2 = col + dx;
            if (c2 < 0 || c2 >= GRID_W) continue;
            int n2 = (y2 << 8) + c2;
            acc = fmaf(ws[dd * 25 + (dy + 2) * 5 + (dx + 2)],
                       v[((size_t)n2 * BD + b) * CD + c], acc);
        }
    }
    dwc[idx] = acc;
}

// ---------------------------------------------------------------------------
// FUSED: focusing(q) + attention matvec + dwc add + bf16 split write
// v2: 32 rows/block, 4 rows/warp — one kv LDS8 now feeds 8 FMAs (4 rows),
// halving crossbar bytes per row and amortizing the kv tile pass.
// smem: rs(768) | kms(64) | kvs(4096) | qs(32 x 776)  = 119040 B (1 CTA/SM)
// ---------------------------------------------------------------------------
#define AT_RS   0
#define AT_KMS  768
#define AT_KVS  832
#define AT_QS   4928
#define AT_QSTR 776
#define AT_ROWS 32
#define ATTN_SMEM ((AT_QS + AT_ROWS * AT_QSTR) * 4)   // 119040 bytes

__global__ __launch_bounds__(256, 1)
void attn_fused(const float* __restrict__ q, const float* __restrict__ rsp,
                const float* __restrict__ kv, const float* __restrict__ km,
                const float* __restrict__ dwc,
                __nv_bfloat162* __restrict__ hi, __nv_bfloat162* __restrict__ lo)
{
    extern __shared__ float sm[];
    float* rs  = sm + AT_RS;
    float* kms = sm + AT_KMS;
    float* kvs = sm + AT_KVS;
    float* qs  = sm + AT_QS;

    const int tid  = threadIdx.x;
    const int wid  = tid >> 5;
    const int lane = tid & 31;
    const int b    = blockIdx.y;
    const int n0   = blockIdx.x * AT_ROWS;

    if (tid < 192) ((float4*)rs)[tid] = ((const float4*)rsp)[tid];

    // load 32 q rows (float4 coalesced): 32*192 = 6144 float4
#pragma unroll
    for (int i = 0; i < 24; i++) {
        int idx = tid + i * 256;
        int r = idx / 192, j = idx % 192;
        float4 vq = *(const float4*)(q + ((size_t)(n0 + r) * BD + b) * CD + j * 4);
        *(float4*)(qs + r * AT_QSTR + j * 4) = vq;
    }
    __syncthreads();

    // focusing nonlinearity: warp w -> rows 4w..4w+3
#pragma unroll
    for (int rr = 0; rr < 4; rr++) {
        const int row = wid * 4 + rr;
        float* qr = qs + row * AT_QSTR;
        float t[24];
        float s2 = 0.f, s6 = 0.f;
#pragma unroll
        for (int jj = 0; jj < 12; jj++) {
            int c = jj * 64 + lane * 2;
            float2 xv = *(float2*)(qr + c);
            float2 rv = *(float2*)(rs + c);
            float x0 = ((xv.x > 0.f ? xv.x : 0.f) + EPSF) * rv.x;
            float x1 = ((xv.y > 0.f ? xv.y : 0.f) + EPSF) * rv.y;
            t[jj * 2]     = x0;
            t[jj * 2 + 1] = x1;
            float p0 = x0 * x0, p1 = x1 * x1;
            s2 += p0 + p1;
            s6 += p0 * p0 * p0 + p1 * p1 * p1;
        }
#pragma unroll
        for (int off = 16; off > 0; off >>= 1) {
            s2 += __shfl_xor_sync(0xffffffffu, s2, off);
            s6 += __shfl_xor_sync(0xffffffffu, s6, off);
        }
        float f = sqrtf(s2) / sqrtf(s6);
#pragma unroll
        for (int jj = 0; jj < 12; jj++) {
            int c = jj * 64 + lane * 2;
            float x0 = t[jj * 2], x1 = t[jj * 2 + 1];
            float2 o = make_float2(x0 * x0 * x0 * f, x1 * x1 * x1 * f);
            *(float2*)(qr + c) = o;
        }
    }
    __syncthreads();

    // per-head: z + 4-row matvec + dwc + split write
    for (int hh = 0; hh < HD; hh++) {
        const int bh = b * HD + hh;
        const float4* kvg = (const float4*)(kv + (size_t)bh * DD * DD);
#pragma unroll
        for (int i = 0; i < 4; i++)
            ((float4*)kvs)[tid + i * 256] = kvg[tid + i * 256];
        if (tid < 16) ((float4*)kms)[tid] = ((const float4*)(km + (size_t)bh * DD))[tid];
        __syncthreads();

        const float* qh0 = qs + (wid * 4 + 0) * AT_QSTR + hh * DD;
        const float* qh1 = qs + (wid * 4 + 1) * AT_QSTR + hh * DD;
        const float* qh2 = qs + (wid * 4 + 2) * AT_QSTR + hh * DD;
        const float* qh3 = qs + (wid * 4 + 3) * AT_QSTR + hh * DD;

        // z for 4 rows
        float z[4];
        {
            float2 k2 = *(float2*)(kms + lane * 2);
#pragma unroll
            for (int r = 0; r < 4; r++) {
                const float* qh = (r == 0) ? qh0 : (r == 1) ? qh1 : (r == 2) ? qh2 : qh3;
                float2 q2 = *(float2*)(qh + lane * 2);
                float pz = q2.x * k2.x + q2.y * k2.y;
#pragma unroll
                for (int off = 16; off > 0; off >>= 1)
                    pz += __shfl_xor_sync(0xffffffffu, pz, off);
                z[r] = 1.f / (pz + EPSF);
            }
        }

        // matvec: one kv LDS8 per dd serves 4 rows
        float ax0 = 0.f, ay0 = 0.f, ax1 = 0.f, ay1 = 0.f;
        float ax2 = 0.f, ay2 = 0.f, ax3 = 0.f, ay3 = 0.f;
#pragma unroll 8
        for (int dd = 0; dd < DD; dd++) {
            float2 kvv = *(float2*)(kvs + dd * DD + lane * 2);
            float q0 = qh0[dd], q1 = qh1[dd], q2v = qh2[dd], q3 = qh3[dd];
            ax0 = fmaf(q0, kvv.x, ax0);  ay0 = fmaf(q0, kvv.y, ay0);
            ax1 = fmaf(q1, kvv.x, ax1);  ay1 = fmaf(q1, kvv.y, ay1);
            ax2 = fmaf(q2v, kvv.x, ax2); ay2 = fmaf(q2v, kvv.y, ay2);
            ax3 = fmaf(q3, kvv.x, ax3);  ay3 = fmaf(q3, kvv.y, ay3);
        }

        float axs[4] = { ax0, ax1, ax2, ax3 };
        float ays[4] = { ay0, ay1, ay2, ay3 };
#pragma unroll
        for (int r = 0; r < 4; r++) {
            const int n = n0 + wid * 4 + r;
            float ax = axs[r] * z[r];
            float ay = ays[r] * z[r];

            int dn = n & (NM - 1);
            float2 dw = *(const float2*)(dwc + ((size_t)dn * BD + b) * CD + hh * DD + lane * 2);
            ax += dw.x; ay += dw.y;

            __nv_bfloat16 h0 = __float2bfloat16(ax);
            __nv_bfloat16 h1 = __float2bfloat16(ay);
            __nv_bfloat16 l0 = __float2bfloat16(ax - __bfloat162float(h0));
            __nv_bfloat16 l1 = __float2bfloat16(ay - __bfloat162float(h1));
            size_t o = (((size_t)n * BD + b) * CD + hh * DD + lane * 2) >> 1;
            hi[o] = __halves2bfloat162(h0, h1);
            lo[o] = __halves2bfloat162(l0, l1);
        }
        __syncthreads();
    }
}

// ---------------------------------------------------------------------------
// kernel_launch
// ---------------------------------------------------------------------------
extern "C" void kernel_launch(void* const* d_in, const int* in_sizes, int n_in,
                              void* d_out, int out_size)
{
    const float* x      = (const float*)d_in[0];
    const float* memory = (const float*)d_in[1];
    const float* w_q    = (const float*)d_in[2];
    const float* w_k    = (const float*)d_in[3];
    const float* w_v    = (const float*)d_in[4];
    const float* w_proj = (const float*)d_in[5];
    const float* b_proj = (const float*)d_in[6];
    const float* dwc_w  = (const float*)d_in[7];
    const float* dwc_b  = (const float*)d_in[8];
    const float* scale  = (const float*)d_in[9];
    float* out = (float*)d_out;

    float *p_q, *p_k, *p_v, *p_dwc, *p_kvp, *p_kmp, *p_kv, *p_km, *p_rsp;
    __nv_bfloat16 *p_ah, *p_al, *p_bh, *p_bl, *p_wh, *p_wl;
    cudaGetSymbolAddress((void**)&p_q,   g_q);
    cudaGetSymbolAddress((void**)&p_k,   g_k);
    cudaGetSymbolAddress((void**)&p_v,   g_v);
    cudaGetSymbolAddress((void**)&p_dwc, g_dwc);
    cudaGetSymbolAddress((void**)&p_kvp, g_kvp);
    cudaGetSymbolAddress((void**)&p_kmp, g_kmp);
    cudaGetSymbolAddress((void**)&p_kv,  g_kv);
    cudaGetSymbolAddress((void**)&p_km,  g_km);
    cudaGetSymbolAddress((void**)&p_rsp, g_rsp);
    cudaGetSymbolAddress((void**)&p_ah,  g_ah);
    cudaGetSymbolAddress((void**)&p_al,  g_al);
    cudaGetSymbolAddress((void**)&p_bh,  g_bh);
    cudaGetSymbolAddress((void**)&p_bl,  g_bl);
    cudaGetSymbolAddress((void**)&p_wh,  g_wh);
    cudaGetSymbolAddress((void**)&p_wl,  g_wl);

    cudaFuncSetAttribute(gemm_mma<false>, cudaFuncAttributeMaxDynamicSharedMemorySize, GEMM_SMEM);
    cudaFuncSetAttribute(gemm_mma<true>,  cudaFuncAttributeMaxDynamicSharedMemorySize, GEMM_SMEM);
    cudaFuncSetAttribute(attn_fused,      cudaFuncAttributeMaxDynamicSharedMemorySize, ATTN_SMEM);

    const int WN4 = CD * CD / 4;

    // launch 1-3
    rsoftplus_kernel<<<3, 256>>>(scale, p_rsp);
    cvt_pair<<<(MQ * CD / 4 + 255) / 256, 256>>>((const float4*)x,
        (__nv_bfloat162*)p_ah, (__nv_bfloat162*)p_al, MQ * CD / 4);
    cvt_weights<<<dim3((WN4 + 255) / 256, 4), 256>>>((const float4*)w_q,
        (const float4*)w_k, (const float4*)w_v, (const float4*)w_proj,
        (__nv_bfloat162*)p_wh, (__nv_bfloat162*)p_wl);

    // launch 4 — Q GEMM (ncu capture target)
    gemm_mma<false><<<dim3(CD / 128, MQ / 128), 256, GEMM_SMEM>>>(
        p_ah, p_al, p_wh + 0 * CD * CD, p_wl + 0 * CD * CD, p_q, p_q, nullptr);

    cvt_pair<<<(MK * CD / 4 + 255) / 256, 256>>>((const float4*)memory,
        (__nv_bfloat162*)p_bh, (__nv_bfloat162*)p_bl, MK * CD / 4);

    // merged K+V GEMM: N = 1536 over concatenated [w_k; w_v]; cols<768 -> k, >=768 -> v
    gemm_mma<false><<<dim3(2 * CD / 128, MK / 128), 256, GEMM_SMEM>>>(
        p_bh, p_bl, p_wh + 1 * CD * CD, p_wl + 1 * CD * CD, p_k, p_v, nullptr);

    // focusing nonlinearity on k (q fused into attn)
    process_kernel<<<MK, 256>>>(p_k, p_rsp);

    // kv + k_mean
    kv_partial_kernel<<<dim3(BD * HD, KVSPLIT), 256>>>(p_k, p_v, p_kvp, p_kmp);
    {
        int tot = BD * HD * DD * DD + BD * HD * DD;
        kv_reduce_kernel<<<(tot + 255) / 256, 256>>>(p_kvp, p_kmp, p_kv, p_km);
    }

    // depthwise conv on v
    {
        size_t tot = (size_t)NM * BD * CD;
        dwconv_kernel<<<(unsigned)(tot / 256), 256>>>(p_v, dwc_w, dwc_b, p_dwc);
    }

    // fused attention -> bf16 split pair (reuses g_ah/g_al)
    attn_fused<<<dim3(NX / AT_ROWS, BD), 256, ATTN_SMEM>>>(
        p_q, p_rsp, p_kv, p_km, p_dwc,
        (__nv_bfloat162*)p_ah, (__nv_bfloat162*)p_al);

    // final projection with fused bias -> d_out
    gemm_mma<true><<<dim3(CD / 128, MQ / 128), 256, GEMM_SMEM>>>(
        p_ah, p_al, p_wh + 3 * CD * CD, p_wl + 3 * CD * CD, out, out, b_proj);
}

// round 12
// speedup vs baseline: 1.4772x; 1.4772x over previous
#include <cuda_runtime.h>
#include <cuda_bf16.h>
#include <math.h>
#include <stdint.h>

// ---------------------------------------------------------------------------
// Problem constants
// ---------------------------------------------------------------------------
#define BD   2
#define CD   768
#define HD   12
#define DD   64
#define NX   16384
#define NM   4096
#define GRID_H 16
#define GRID_W 256
#define EPSF 1e-6f
#define KVSPLIT 16

#define MQ (NX * BD)   // 32768
#define MK (NM * BD)   // 8192

// ---------------------------------------------------------------------------
// Scratch (__device__ globals; no cudaMalloc allowed)
// ---------------------------------------------------------------------------
__device__ float g_q  [(size_t)MQ * CD];
__device__ float g_k  [(size_t)MK * CD];
__device__ float g_v  [(size_t)MK * CD];
__device__ float g_dwc[(size_t)MK * CD];
__device__ float g_kvp[(size_t)KVSPLIT * BD * HD * DD * DD];
__device__ float g_kmp[(size_t)KVSPLIT * BD * HD * DD];
__device__ float g_kv [(size_t)BD * HD * DD * DD];
__device__ float g_km [(size_t)BD * HD * DD];
__device__ float g_rsp[CD];                      // 1/softplus(scale)

// bf16 split-pair buffers
__device__ __nv_bfloat16 g_ah[(size_t)MQ * CD];  // x hi (reused for attn output hi)
__device__ __nv_bfloat16 g_al[(size_t)MQ * CD];  // x lo (reused for attn output lo)
__device__ __nv_bfloat16 g_bh[(size_t)MK * CD];  // memory hi
__device__ __nv_bfloat16 g_bl[(size_t)MK * CD];  // memory lo
__device__ __nv_bfloat16 g_wh[4 * CD * CD];      // wq, wk, wv, wproj hi (contiguous)
__device__ __nv_bfloat16 g_wl[4 * CD * CD];      // lo

// ---------------------------------------------------------------------------
// PTX helpers (family-safe: mma.sync + cp.async + ldmatrix)
// ---------------------------------------------------------------------------
__device__ __forceinline__ uint32_t smem_u32(const void* p) {
    uint32_t a;
    asm("{ .reg .u64 t; cvta.to.shared.u64 t, %1; cvt.u32.u64 %0, t; }"
        : "=r"(a) : "l"(p));
    return a;
}

// NOTE: .ca is load-bearing — .cg regressed the GEMM 315->509us (round 8).
// NOTE: 2-stage + STR40 padding is the proven-fast config; 3-stage swizzle
//       regressed (round 10). attn_fused 32-row variant regressed (round 11).
#define CP_ASYNC16(dst, src) \
    asm volatile("cp.async.ca.shared.global [%0], [%1], 16;" :: "r"(dst), "l"(src))
#define CP_COMMIT() asm volatile("cp.async.commit_group;")
#define CP_WAIT1()  asm volatile("cp.async.wait_group 1;")
#define CP_WAIT0()  asm volatile("cp.async.wait_group 0;")

#define MMA_BF16(c, a, b) \
    asm volatile( \
        "mma.sync.aligned.m16n8k16.row.col.f32.bf16.bf16.f32 " \
        "{%0,%1,%2,%3}, {%4,%5,%6,%7}, {%8,%9}, {%0,%1,%2,%3};" \
        : "+f"((c)[0]), "+f"((c)[1]), "+f"((c)[2]), "+f"((c)[3]) \
        : "r"((a)[0]), "r"((a)[1]), "r"((a)[2]), "r"((a)[3]), \
          "r"((b)[0]), "r"((b)[1]))

#define LDSM4(r, addr) \
    asm volatile("ldmatrix.sync.aligned.m8n8.x4.shared.b16 {%0,%1,%2,%3}, [%4];" \
        : "=r"((r)[0]), "=r"((r)[1]), "=r"((r)[2]), "=r"((r)[3]) : "r"(addr))

// ---------------------------------------------------------------------------
// HMMA split-bf16 GEMM (round-9 config): C[M,N'] = (Ah+Al)*(Wh+Wl)^T
// CTA tile 128x128, BK=32, 8 warps (4m x 2n), 2 stages, STR=40 padding,
// 2 CTAs/SM. Dual-output epilogue for merged K/V GEMM.
// ---------------------------------------------------------------------------
#define STR     40
#define TILE_B  (128 * STR * 2)          // 10240 bytes
#define STAGE_B (4 * TILE_B)             // 40960
#define GEMM_SMEM (2 * STAGE_B)          // 81920
#define NCHUNK  (CD / 32)                // 24

template<bool BIAS>
__global__ __launch_bounds__(256, 2)
void gemm_mma(const __nv_bfloat16* __restrict__ Ah, const __nv_bfloat16* __restrict__ Al,
              const __nv_bfloat16* __restrict__ Wh, const __nv_bfloat16* __restrict__ Wl,
              float* __restrict__ C0, float* __restrict__ C1,
              const float* __restrict__ bias)
{
    extern __shared__ char smem[];
    const uint32_t sb = smem_u32(smem);
    const int tid  = threadIdx.x;
    const int wid  = tid >> 5;
    const int lane = tid & 31;
    const int n0 = blockIdx.x * 128;
    const int m0 = blockIdx.y * 128;

    const int moff = (wid & 3) * 32;
    const int noff = (wid >> 2) * 64;
    const int gid  = lane >> 2;
    const int qid  = lane & 3;

    const int lq = lane >> 3;
    const int lr = lane & 7;
    const int a_row = (lq & 1) * 8 + lr;
    const int a_kc  = (lq >> 1) * 8;
    const int b_row = (lq >> 1) * 8 + lr;
    const int b_kc  = (lq & 1) * 8;

    const __nv_bfloat16* srcs[4] = { Ah, Al, Wh, Wl };
    const int brow[4] = { m0, m0, n0, n0 };

    auto load_chunk = [&](int kc, int st) {
#pragma unroll
        for (int t = 0; t < 4; t++) {
            const __nv_bfloat16* src = srcs[t];
#pragma unroll
            for (int i = 0; i < 2; i++) {
                int idx = tid + i * 256;
                int row = idx >> 2;
                int seg = idx & 3;
                const __nv_bfloat16* g = src + (size_t)(brow[t] + row) * CD + kc + seg * 8;
                uint32_t d = sb + st * STAGE_B + t * TILE_B + (row * STR + seg * 8) * 2;
                CP_ASYNC16(d, g);
            }
        }
        CP_COMMIT();
    };

    float acc[2][8][4];
#pragma unroll
    for (int mt = 0; mt < 2; mt++)
#pragma unroll
        for (int nt = 0; nt < 8; nt++)
#pragma unroll
            for (int j = 0; j < 4; j++) acc[mt][nt][j] = 0.f;

    load_chunk(0, 0);
    load_chunk(32, 1);

    for (int c = 0; c < NCHUNK; c++) {
        if (c < NCHUNK - 1) { CP_WAIT1(); } else { CP_WAIT0(); }
        __syncthreads();

        const int st = c & 1;
        const uint32_t sAh = sb + st * STAGE_B + 0 * TILE_B;
        const uint32_t sAl = sb + st * STAGE_B + 1 * TILE_B;
        const uint32_t sWh = sb + st * STAGE_B + 2 * TILE_B;
        const uint32_t sWl = sb + st * STAGE_B + 3 * TILE_B;

#pragma unroll
        for (int ks = 0; ks < 2; ks++) {
            const int kb = ks * 16;

            uint32_t a[2][4], al2[2][4];
#pragma unroll
            for (int mt = 0; mt < 2; mt++) {
                uint32_t ra = ((moff + mt * 16 + a_row) * STR + kb + a_kc) * 2;
                LDSM4(a[mt],   sAh + ra);
                LDSM4(al2[mt], sAl + ra);
            }

            uint32_t bh[4][4], bl[4][4];
#pragma unroll
            for (int p = 0; p < 4; p++) {
                uint32_t rb = ((noff + p * 16 + b_row) * STR + kb + b_kc) * 2;
                LDSM4(bh[p], sWh + rb);
                LDSM4(bl[p], sWl + rb);
            }

#pragma unroll
            for (int mt = 0; mt < 2; mt++)
#pragma unroll
                for (int nt = 0; nt < 8; nt++) {
                    MMA_BF16(acc[mt][nt], a[mt],   &bh[nt >> 1][(nt & 1) * 2]);
                    MMA_BF16(acc[mt][nt], a[mt],   &bl[nt >> 1][(nt & 1) * 2]);
                    MMA_BF16(acc[mt][nt], al2[mt], &bh[nt >> 1][(nt & 1) * 2]);
                }
        }

        __syncthreads();
        if (c + 2 < NCHUNK) load_chunk((c + 2) * 32, st);
    }

    // ---- epilogue: route to C0 (cols < 768) or C1 (cols >= 768) ----
    float* Cb = C0;
    int nb = n0;
    if (n0 >= CD) { Cb = C1; nb = n0 - CD; }

#pragma unroll
    for (int mt = 0; mt < 2; mt++) {
        int r0 = m0 + moff + mt * 16 + gid;
#pragma unroll
        for (int nt = 0; nt < 8; nt++) {
            int col = nb + noff + nt * 8 + qid * 2;
            float b0 = 0.f, b1 = 0.f;
            if (BIAS) { b0 = __ldg(bias + col); b1 = __ldg(bias + col + 1); }
            float2 v0 = make_float2(acc[mt][nt][0] + b0, acc[mt][nt][1] + b1);
            float2 v1 = make_float2(acc[mt][nt][2] + b0, acc[mt][nt][3] + b1);
            *(float2*)(Cb + (size_t)r0 * CD + col)       = v0;
            *(float2*)(Cb + (size_t)(r0 + 8) * CD + col) = v1;
        }
    }
}

// ---------------------------------------------------------------------------
// fp32 -> (bf16 hi, bf16 lo) split conversion
// ---------------------------------------------------------------------------
__global__ void cvt_pair(const float4* __restrict__ src,
                         __nv_bfloat162* __restrict__ hi,
                         __nv_bfloat162* __restrict__ lo, int n4)
{
    int i = blockIdx.x * blockDim.x + threadIdx.x;
    if (i >= n4) return;
    float4 v = src[i];
    __nv_bfloat16 h0 = __float2bfloat16(v.x), h1 = __float2bfloat16(v.y);
    __nv_bfloat16 h2 = __float2bfloat16(v.z), h3 = __float2bfloat16(v.w);
    __nv_bfloat16 l0 = __float2bfloat16(v.x - __bfloat162float(h0));
    __nv_bfloat16 l1 = __float2bfloat16(v.y - __bfloat162float(h1));
    __nv_bfloat16 l2 = __float2bfloat16(v.z - __bfloat162float(h2));
    __nv_bfloat16 l3 = __float2bfloat16(v.w - __bfloat162float(h3));
    hi[2 * i]     = __halves2bfloat162(h0, h1);
    hi[2 * i + 1] = __halves2bfloat162(h2, h3);
    lo[2 * i]     = __halves2bfloat162(l0, l1);
    lo[2 * i + 1] = __halves2bfloat162(l2, l3);
}

// merged conversion of all 4 weight matrices (blockIdx.y selects tensor)
__global__ void cvt_weights(const float4* __restrict__ w0, const float4* __restrict__ w1,
                            const float4* __restrict__ w2, const float4* __restrict__ w3,
                            __nv_bfloat162* __restrict__ hi, __nv_bfloat162* __restrict__ lo)
{
    const int n4 = CD * CD / 4;
    int i = blockIdx.x * blockDim.x + threadIdx.x;
    if (i >= n4) return;
    const float4* src = (blockIdx.y == 0) ? w0 : (blockIdx.y == 1) ? w1
                      : (blockIdx.y == 2) ? w2 : w3;
    size_t o = (size_t)blockIdx.y * (CD * CD / 2);
    float4 v = src[i];
    __nv_bfloat16 h0 = __float2bfloat16(v.x), h1 = __float2bfloat16(v.y);
    __nv_bfloat16 h2 = __float2bfloat16(v.z), h3 = __float2bfloat16(v.w);
    __nv_bfloat16 l0 = __float2bfloat16(v.x - __bfloat162float(h0));
    __nv_bfloat16 l1 = __float2bfloat16(v.y - __bfloat162float(h1));
    __nv_bfloat16 l2 = __float2bfloat16(v.z - __bfloat162float(h2));
    __nv_bfloat16 l3 = __float2bfloat16(v.w - __bfloat162float(h3));
    hi[o + 2 * i]     = __halves2bfloat162(h0, h1);
    hi[o + 2 * i + 1] = __halves2bfloat162(h2, h3);
    lo[o + 2 * i]     = __halves2bfloat162(l0, l1);
    lo[o + 2 * i + 1] = __halves2bfloat162(l2, l3);
}

// ---------------------------------------------------------------------------
// 1/softplus(scale)
// ---------------------------------------------------------------------------
__global__ void rsoftplus_kernel(const float* __restrict__ scale, float* __restrict__ rsp)
{
    int c = blockIdx.x * blockDim.x + threadIdx.x;
    if (c < CD) {
        float s = scale[c];
        float sp = (s > 20.f) ? s : log1pf(expf(s));
        rsp[c] = 1.f / sp;
    }
}

// ---------------------------------------------------------------------------
// Focusing nonlinearity for k (in-place)
// ---------------------------------------------------------------------------
__global__ __launch_bounds__(256) void process_kernel(float* __restrict__ t,
                                                      const float* __restrict__ rsp)
{
    float* row = t + (size_t)blockIdx.x * CD;
    const int tid = threadIdx.x;

    float v[3];
    float s2 = 0.f, s6 = 0.f;
#pragma unroll
    for (int i = 0; i < 3; i++) {
        int c = tid + i * 256;
        float x = row[c];
        x = (x > 0.f ? x : 0.f) + EPSF;
        x = x * rsp[c];
        v[i] = x;
        float x2 = x * x;
        s2 += x2;
        s6 += x2 * x2 * x2;
    }
#pragma unroll
    for (int off = 16; off > 0; off >>= 1) {
        s2 += __shfl_xor_sync(0xffffffffu, s2, off);
        s6 += __shfl_xor_sync(0xffffffffu, s6, off);
    }
    __shared__ float sA[8], sB[8];
    int warp = tid >> 5, lane = tid & 31;
    if (lane == 0) { sA[warp] = s2; sB[warp] = s6; }
    __syncthreads();
    if (warp == 0) {
        float a = (lane < 8) ? sA[lane] : 0.f;
        float b = (lane < 8) ? sB[lane] : 0.f;
#pragma unroll
        for (int off = 4; off > 0; off >>= 1) {
            a += __shfl_xor_sync(0xffffffffu, a, off);
            b += __shfl_xor_sync(0xffffffffu, b, off);
        }
        if (lane == 0) { sA[0] = a; sB[0] = b; }
    }
    __syncthreads();
    float f = sqrtf(sA[0]) / sqrtf(sB[0]);
#pragma unroll
    for (int i = 0; i < 3; i++) {
        int c = tid + i * 256;
        row[c] = v[i] * v[i] * v[i] * f;
    }
}

// ---------------------------------------------------------------------------
// kv partial + reduce
// ---------------------------------------------------------------------------
__global__ __launch_bounds__(256) void kv_partial_kernel(const float* __restrict__ k,
                                                         const float* __restrict__ v,
                                                         float* __restrict__ kvp,
                                                         float* __restrict__ kmp)
{
    const int bh = blockIdx.x;
    const int b  = bh / HD;
    const int hh = bh % HD;
    const int n0 = blockIdx.y * (NM / KVSPLIT);
    const int t  = threadIdx.x;
    const int d1 = t >> 2;
    const int c0 = (t & 3) * 16;

    __shared__ float ks[DD], vs[DD];

    float acc[16];
#pragma unroll
    for (int j = 0; j < 16; j++) acc[j] = 0.f;
    float ksum = 0.f;

    for (int n = n0; n < n0 + NM / KVSPLIT; n++) {
        size_t base = ((size_t)n * BD + b) * CD + hh * DD;
        if (t < DD)           ks[t]      = k[base + t];
        else if (t < 2 * DD)  vs[t - DD] = v[base + t - DD];
        __syncthreads();
        float kd = ks[d1];
#pragma unroll
        for (int j = 0; j < 16; j++) acc[j] = fmaf(kd, vs[c0 + j], acc[j]);
        if (t < DD) ksum += ks[t];
        __syncthreads();
    }

    const float s = 1.f / (float)NM;
    float* outp = kvp + ((size_t)blockIdx.y * (BD * HD) + bh) * (DD * DD) + d1 * DD + c0;
#pragma unroll
    for (int j = 0; j < 16; j++) outp[j] = acc[j] * s;
    if (t < DD) kmp[((size_t)blockIdx.y * (BD * HD) + bh) * DD + t] = ksum * s;
}

__global__ void kv_reduce_kernel(const float* __restrict__ kvp, const float* __restrict__ kmp,
                                 float* __restrict__ kv, float* __restrict__ km)
{
    int idx = blockIdx.x * blockDim.x + threadIdx.x;
    const int NKV = BD * HD * DD * DD;
    const int NKM = BD * HD * DD;
    if (idx < NKV) {
        float s = 0.f;
#pragma unroll
        for (int p = 0; p < KVSPLIT; p++) s += kvp[(size_t)p * NKV + idx];
        kv[idx] = s;
    } else if (idx < NKV + NKM) {
        int i = idx - NKV;
        float s = 0.f;
#pragma unroll
        for (int p = 0; p < KVSPLIT; p++) s += kmp[(size_t)p * NKM + i];
        km[i] = s;
    }
}

// ---------------------------------------------------------------------------
// depthwise 5x5 conv (bias included)
// ---------------------------------------------------------------------------
__global__ __launch_bounds__(256) void dwconv_kernel(const float* __restrict__ v,
                                                     const float* __restrict__ w,
                                                     const float* __restrict__ bias,
                                                     float* __restrict__ dwc)
{
    __shared__ float ws[DD * 25];
    __shared__ float bs[DD];
    const int t = threadIdx.x;
    for (int i = t; i < DD * 25; i += 256) ws[i] = w[i];
    if (t < DD) bs[t] = bias[t];
    __syncthreads();

    size_t idx = (size_t)blockIdx.x * 256 + t;
    int c  = (int)(idx % CD);
    int rb = (int)(idx / CD);
    int b  = rb & 1;
    int n  = rb >> 1;
    int y   = n >> 8;
    int col = n & 255;
    int dd  = c & (DD - 1);

    float acc = bs[dd];
#pragma unroll
    for (int dy = -2; dy <= 2; dy++) {
        int y2 = y + dy;
        if (y2 < 0 || y2 >= GRID_H) continue;
#pragma unroll
        for (int dx = -2; dx <= 2; dx++) {
            int c2 = col + dx;
            if (c2 < 0 || c2 >= GRID_W) continue;
            int n2 = (y2 << 8) + c2;
            acc = fmaf(ws[dd * 25 + (dy + 2) * 5 + (dx + 2)],
                       v[((size_t)n2 * BD + b) * CD + c], acc);
        }
    }
    dwc[idx] = acc;
}

// ---------------------------------------------------------------------------
// FUSED: focusing(q) + attention matvec + dwc add + bf16 split write
// (round-9 v1: 16 rows/block, 2 rows/warp, 69KB smem, 2 CTAs/SM — proven)
// ---------------------------------------------------------------------------
#define AT_RS   0
#define AT_KMS  768
#define AT_KVS  832
#define AT_QS   4928
#define AT_QSTR 776
#define ATTN_SMEM ((AT_QS + 16 * AT_QSTR) * 4)   // 69376 bytes

__global__ __launch_bounds__(256, 2)
void attn_fused(const float* __restrict__ q, const float* __restrict__ rsp,
                const float* __restrict__ kv, const float* __restrict__ km,
                const float* __restrict__ dwc,
                __nv_bfloat162* __restrict__ hi, __nv_bfloat162* __restrict__ lo)
{
    extern __shared__ float sm[];
    float* rs  = sm + AT_RS;
    float* kms = sm + AT_KMS;
    float* kvs = sm + AT_KVS;
    float* qs  = sm + AT_QS;

    const int tid  = threadIdx.x;
    const int wid  = tid >> 5;
    const int lane = tid & 31;
    const int b    = blockIdx.y;
    const int n0   = blockIdx.x * 16;

    if (tid < 192) ((float4*)rs)[tid] = ((const float4*)rsp)[tid];

#pragma unroll
    for (int i = 0; i < 12; i++) {
        int idx = tid + i * 256;
        int r = idx / 192, j = idx % 192;
        float4 vq = *(const float4*)(q + ((size_t)(n0 + r) * BD + b) * CD + j * 4);
        *(float4*)(qs + r * AT_QSTR + j * 4) = vq;
    }
    __syncthreads();

#pragma unroll
    for (int rr = 0; rr < 2; rr++) {
        const int row = wid * 2 + rr;
        float* qr = qs + row * AT_QSTR;
        float t[24];
        float s2 = 0.f, s6 = 0.f;
#pragma unroll
        for (int jj = 0; jj < 12; jj++) {
            int c = jj * 64 + lane * 2;
            float2 xv = *(float2*)(qr + c);
            float2 rv = *(float2*)(rs + c);
            float x0 = ((xv.x > 0.f ? xv.x : 0.f) + EPSF) * rv.x;
            float x1 = ((xv.y > 0.f ? xv.y : 0.f) + EPSF) * rv.y;
            t[jj * 2]     = x0;
            t[jj * 2 + 1] = x1;
            float p0 = x0 * x0, p1 = x1 * x1;
            s2 += p0 + p1;
            s6 += p0 * p0 * p0 + p1 * p1 * p1;
        }
#pragma unroll
        for (int off = 16; off > 0; off >>= 1) {
            s2 += __shfl_xor_sync(0xffffffffu, s2, off);
            s6 += __shfl_xor_sync(0xffffffffu, s6, off);
        }
        float f = sqrtf(s2) / sqrtf(s6);
#pragma unroll
        for (int jj = 0; jj < 12; jj++) {
            int c = jj * 64 + lane * 2;
            float x0 = t[jj * 2], x1 = t[jj * 2 + 1];
            float2 o = make_float2(x0 * x0 * x0 * f, x1 * x1 * x1 * f);
            *(float2*)(qr + c) = o;
        }
    }
    __syncthreads();

    for (int hh = 0; hh < HD; hh++) {
        const int bh = b * HD + hh;
        const float4* kvg = (const float4*)(kv + (size_t)bh * DD * DD);
#pragma unroll
        for (int i = 0; i < 4; i++)
            ((float4*)kvs)[tid + i * 256] = kvg[tid + i * 256];
        if (tid < 16) ((float4*)kms)[tid] = ((const float4*)(km + (size_t)bh * DD))[tid];
        __syncthreads();

#pragma unroll
        for (int rr = 0; rr < 2; rr++) {
            const int row = wid * 2 + rr;
            const int n = n0 + row;
            const float* qh = qs + row * AT_QSTR + hh * DD;

            float2 q2 = *(float2*)(qh + lane * 2);
            float2 k2 = *(float2*)(kms + lane * 2);
            float pz = q2.x * k2.x + q2.y * k2.y;
#pragma unroll
            for (int off = 16; off > 0; off >>= 1)
                pz += __shfl_xor_sync(0xffffffffu, pz, off);
            float z = 1.f / (pz + EPSF);

            float ax = 0.f, ay = 0.f;
#pragma unroll 8
            for (int dd = 0; dd < DD; dd++) {
                float qd = qh[dd];
                float2 kvv = *(float2*)(kvs + dd * DD + lane * 2);
                ax = fmaf(qd, kvv.x, ax);
                ay = fmaf(qd, kvv.y, ay);
            }
            ax *= z; ay *= z;

            int dn = n & (NM - 1);
            float2 dw = *(const float2*)(dwc + ((size_t)dn * BD + b) * CD + hh * DD + lane * 2);
            ax += dw.x; ay += dw.y;

            __nv_bfloat16 h0 = __float2bfloat16(ax);
            __nv_bfloat16 h1 = __float2bfloat16(ay);
            __nv_bfloat16 l0 = __float2bfloat16(ax - __bfloat162float(h0));
            __nv_bfloat16 l1 = __float2bfloat16(ay - __bfloat162float(h1));
            size_t o = (((size_t)n * BD + b) * CD + hh * DD + lane * 2) >> 1;
            hi[o] = __halves2bfloat162(h0, h1);
            lo[o] = __halves2bfloat162(l0, l1);
        }
        __syncthreads();
    }
}

// ---------------------------------------------------------------------------
// kernel_launch — two-branch graph: Q chain || KV chain, join before attn.
// Streams/events are host-side handles created once (no device memory).
// ---------------------------------------------------------------------------
extern "C" void kernel_launch(void* const* d_in, const int* in_sizes, int n_in,
                              void* d_out, int out_size)
{
    const float* x      = (const float*)d_in[0];
    const float* memory = (const float*)d_in[1];
    const float* w_q    = (const float*)d_in[2];
    const float* w_k    = (const float*)d_in[3];
    const float* w_v    = (const float*)d_in[4];
    const float* w_proj = (const float*)d_in[5];
    const float* b_proj = (const float*)d_in[6];
    const float* dwc_w  = (const float*)d_in[7];
    const float* dwc_b  = (const float*)d_in[8];
    const float* scale  = (const float*)d_in[9];
    float* out = (float*)d_out;

    float *p_q, *p_k, *p_v, *p_dwc, *p_kvp, *p_kmp, *p_kv, *p_km, *p_rsp;
    __nv_bfloat16 *p_ah, *p_al, *p_bh, *p_bl, *p_wh, *p_wl;
    cudaGetSymbolAddress((void**)&p_q,   g_q);
    cudaGetSymbolAddress((void**)&p_k,   g_k);
    cudaGetSymbolAddress((void**)&p_v,   g_v);
    cudaGetSymbolAddress((void**)&p_dwc, g_dwc);
    cudaGetSymbolAddress((void**)&p_kvp, g_kvp);
    cudaGetSymbolAddress((void**)&p_kmp, g_kmp);
    cudaGetSymbolAddress((void**)&p_kv,  g_kv);
    cudaGetSymbolAddress((void**)&p_km,  g_km);
    cudaGetSymbolAddress((void**)&p_rsp, g_rsp);
    cudaGetSymbolAddress((void**)&p_ah,  g_ah);
    cudaGetSymbolAddress((void**)&p_al,  g_al);
    cudaGetSymbolAddress((void**)&p_bh,  g_bh);
    cudaGetSymbolAddress((void**)&p_bl,  g_bl);
    cudaGetSymbolAddress((void**)&p_wh,  g_wh);
    cudaGetSymbolAddress((void**)&p_wl,  g_wl);

    cudaFuncSetAttribute(gemm_mma<false>, cudaFuncAttributeMaxDynamicSharedMemorySize, GEMM_SMEM);
    cudaFuncSetAttribute(gemm_mma<true>,  cudaFuncAttributeMaxDynamicSharedMemorySize, GEMM_SMEM);
    cudaFuncSetAttribute(attn_fused,      cudaFuncAttributeMaxDynamicSharedMemorySize, ATTN_SMEM);

    // One-time host-side handles (no device memory involved).
    static cudaStream_t s2 = nullptr;
    static cudaEvent_t evFork = nullptr, evJoin = nullptr;
    if (s2 == nullptr) {
        cudaStreamCreateWithFlags(&s2, cudaStreamNonBlocking);
        cudaEventCreateWithFlags(&evFork, cudaEventDisableTiming);
        cudaEventCreateWithFlags(&evJoin, cudaEventDisableTiming);
    }

    const int WN4 = CD * CD / 4;

    // ---- common prologue (main stream) ----
    rsoftplus_kernel<<<3, 256>>>(scale, p_rsp);
    cvt_weights<<<dim3((WN4 + 255) / 256, 4), 256>>>((const float4*)w_q,
        (const float4*)w_k, (const float4*)w_v, (const float4*)w_proj,
        (__nv_bfloat162*)p_wh, (__nv_bfloat162*)p_wl);
    cvt_pair<<<(MQ * CD / 4 + 255) / 256, 256>>>((const float4*)x,
        (__nv_bfloat162*)p_ah, (__nv_bfloat162*)p_al, MQ * CD / 4);

    // ---- fork: KV chain on s2 ----
    cudaEventRecord(evFork, 0);
    cudaStreamWaitEvent(s2, evFork, 0);

    cvt_pair<<<(MK * CD / 4 + 255) / 256, 256, 0, s2>>>((const float4*)memory,
        (__nv_bfloat162*)p_bh, (__nv_bfloat162*)p_bl, MK * CD / 4);
    gemm_mma<false><<<dim3(2 * CD / 128, MK / 128), 256, GEMM_SMEM, s2>>>(
        p_bh, p_bl, p_wh + 1 * CD * CD, p_wl + 1 * CD * CD, p_k, p_v, nullptr);
    process_kernel<<<MK, 256, 0, s2>>>(p_k, p_rsp);
    kv_partial_kernel<<<dim3(BD * HD, KVSPLIT), 256, 0, s2>>>(p_k, p_v, p_kvp, p_kmp);
    {
        int tot = BD * HD * DD * DD + BD * HD * DD;
        kv_reduce_kernel<<<(tot + 255) / 256, 256, 0, s2>>>(p_kvp, p_kmp, p_kv, p_km);
    }
    {
        size_t tot = (size_t)NM * BD * CD;
        dwconv_kernel<<<(unsigned)(tot / 256), 256, 0, s2>>>(p_v, dwc_w, dwc_b, p_dwc);
    }
    cudaEventRecord(evJoin, s2);

    // ---- Q chain on main stream (concurrent with s2) ----
    gemm_mma<false><<<dim3(CD / 128, MQ / 128), 256, GEMM_SMEM>>>(
        p_ah, p_al, p_wh + 0 * CD * CD, p_wl + 0 * CD * CD, p_q, p_q, nullptr);

    // ---- join, then attn + final projection ----
    cudaStreamWaitEvent(0, evJoin, 0);

    attn_fused<<<dim3(NX / 16, BD), 256, ATTN_SMEM>>>(
        p_q, p_rsp, p_kv, p_km, p_dwc,
        (__nv_bfloat162*)p_ah, (__nv_bfloat162*)p_al);

    gemm_mma<true><<<dim3(CD / 128, MQ / 128), 256, GEMM_SMEM>>>(
        p_ah, p_al, p_wh + 3 * CD * CD, p_wl + 3 * CD * CD, out, out, b_proj);
}

// round 13
// speedup vs baseline: 1.5574x; 1.0543x over previous
#include <cuda_runtime.h>
#include <cuda_bf16.h>
#include <math.h>
#include <stdint.h>

// ---------------------------------------------------------------------------
// Problem constants
// ---------------------------------------------------------------------------
#define BD   2
#define CD   768
#define HD   12
#define DD   64
#define NX   16384
#define NM   4096
#define GRID_H 16
#define GRID_W 256
#define EPSF 1e-6f
#define KVSPLIT 16

#define MQ (NX * BD)   // 32768
#define MK (NM * BD)   // 8192

// ---------------------------------------------------------------------------
// Scratch (__device__ globals; no cudaMalloc allowed)
// ---------------------------------------------------------------------------
__device__ float g_q  [(size_t)MQ * CD];
__device__ float g_k  [(size_t)MK * CD];
__device__ float g_v  [(size_t)MK * CD];
__device__ float g_dwc[(size_t)MK * CD];
__device__ float g_kvp[(size_t)KVSPLIT * BD * HD * DD * DD];
__device__ float g_kmp[(size_t)KVSPLIT * BD * HD * DD];
__device__ float g_kv [(size_t)BD * HD * DD * DD];
__device__ float g_km [(size_t)BD * HD * DD];
__device__ float g_rsp[CD];                      // 1/softplus(scale)

// bf16 split-pair buffers
__device__ __nv_bfloat16 g_ah[(size_t)MQ * CD];  // x hi (reused for attn output hi)
__device__ __nv_bfloat16 g_al[(size_t)MQ * CD];  // x lo (reused for attn output lo)
__device__ __nv_bfloat16 g_bh[(size_t)MK * CD];  // memory hi
__device__ __nv_bfloat16 g_bl[(size_t)MK * CD];  // memory lo
__device__ __nv_bfloat16 g_wh[4 * CD * CD];      // wq, wk, wv, wproj hi (contiguous)
__device__ __nv_bfloat16 g_wl[4 * CD * CD];      // lo

// ---------------------------------------------------------------------------
// PTX helpers (family-safe: mma.sync + cp.async + ldmatrix)
// ---------------------------------------------------------------------------
__device__ __forceinline__ uint32_t smem_u32(const void* p) {
    uint32_t a;
    asm("{ .reg .u64 t; cvta.to.shared.u64 t, %1; cvt.u32.u64 %0, t; }"
        : "=r"(a) : "l"(p));
    return a;
}

// NOTE: .ca is load-bearing — .cg regressed the GEMM 315->509us (round 8).
// NOTE: 2-stage + STR40 padding is the proven-fast config; 3-stage swizzle
//       regressed (round 10). attn_fused 32-row variant regressed (round 11).
#define CP_ASYNC16(dst, src) \
    asm volatile("cp.async.ca.shared.global [%0], [%1], 16;" :: "r"(dst), "l"(src))
#define CP_COMMIT() asm volatile("cp.async.commit_group;")
#define CP_WAIT1()  asm volatile("cp.async.wait_group 1;")
#define CP_WAIT0()  asm volatile("cp.async.wait_group 0;")

#define MMA_BF16(c, a, b) \
    asm volatile( \
        "mma.sync.aligned.m16n8k16.row.col.f32.bf16.bf16.f32 " \
        "{%0,%1,%2,%3}, {%4,%5,%6,%7}, {%8,%9}, {%0,%1,%2,%3};" \
        : "+f"((c)[0]), "+f"((c)[1]), "+f"((c)[2]), "+f"((c)[3]) \
        : "r"((a)[0]), "r"((a)[1]), "r"((a)[2]), "r"((a)[3]), \
          "r"((b)[0]), "r"((b)[1]))

#define LDSM4(r, addr) \
    asm volatile("ldmatrix.sync.aligned.m8n8.x4.shared.b16 {%0,%1,%2,%3}, [%4];" \
        : "=r"((r)[0]), "=r"((r)[1]), "=r"((r)[2]), "=r"((r)[3]) : "r"(addr))

// ---------------------------------------------------------------------------
// HMMA split-bf16 GEMM (round-9 config, FROZEN): C[M,N'] = (Ah+Al)*(Wh+Wl)^T
// ---------------------------------------------------------------------------
#define STR     40
#define TILE_B  (128 * STR * 2)          // 10240 bytes
#define STAGE_B (4 * TILE_B)             // 40960
#define GEMM_SMEM (2 * STAGE_B)          // 81920
#define NCHUNK  (CD / 32)                // 24

template<bool BIAS>
__global__ __launch_bounds__(256, 2)
void gemm_mma(const __nv_bfloat16* __restrict__ Ah, const __nv_bfloat16* __restrict__ Al,
              const __nv_bfloat16* __restrict__ Wh, const __nv_bfloat16* __restrict__ Wl,
              float* __restrict__ C0, float* __restrict__ C1,
              const float* __restrict__ bias)
{
    extern __shared__ char smem[];
    const uint32_t sb = smem_u32(smem);
    const int tid  = threadIdx.x;
    const int wid  = tid >> 5;
    const int lane = tid & 31;
    const int n0 = blockIdx.x * 128;
    const int m0 = blockIdx.y * 128;

    const int moff = (wid & 3) * 32;
    const int noff = (wid >> 2) * 64;
    const int gid  = lane >> 2;
    const int qid  = lane & 3;

    const int lq = lane >> 3;
    const int lr = lane & 7;
    const int a_row = (lq & 1) * 8 + lr;
    const int a_kc  = (lq >> 1) * 8;
    const int b_row = (lq >> 1) * 8 + lr;
    const int b_kc  = (lq & 1) * 8;

    const __nv_bfloat16* srcs[4] = { Ah, Al, Wh, Wl };
    const int brow[4] = { m0, m0, n0, n0 };

    auto load_chunk = [&](int kc, int st) {
#pragma unroll
        for (int t = 0; t < 4; t++) {
            const __nv_bfloat16* src = srcs[t];
#pragma unroll
            for (int i = 0; i < 2; i++) {
                int idx = tid + i * 256;
                int row = idx >> 2;
                int seg = idx & 3;
                const __nv_bfloat16* g = src + (size_t)(brow[t] + row) * CD + kc + seg * 8;
                uint32_t d = sb + st * STAGE_B + t * TILE_B + (row * STR + seg * 8) * 2;
                CP_ASYNC16(d, g);
            }
        }
        CP_COMMIT();
    };

    float acc[2][8][4];
#pragma unroll
    for (int mt = 0; mt < 2; mt++)
#pragma unroll
        for (int nt = 0; nt < 8; nt++)
#pragma unroll
            for (int j = 0; j < 4; j++) acc[mt][nt][j] = 0.f;

    load_chunk(0, 0);
    load_chunk(32, 1);

    for (int c = 0; c < NCHUNK; c++) {
        if (c < NCHUNK - 1) { CP_WAIT1(); } else { CP_WAIT0(); }
        __syncthreads();

        const int st = c & 1;
        const uint32_t sAh = sb + st * STAGE_B + 0 * TILE_B;
        const uint32_t sAl = sb + st * STAGE_B + 1 * TILE_B;
        const uint32_t sWh = sb + st * STAGE_B + 2 * TILE_B;
        const uint32_t sWl = sb + st * STAGE_B + 3 * TILE_B;

#pragma unroll
        for (int ks = 0; ks < 2; ks++) {
            const int kb = ks * 16;

            uint32_t a[2][4], al2[2][4];
#pragma unroll
            for (int mt = 0; mt < 2; mt++) {
                uint32_t ra = ((moff + mt * 16 + a_row) * STR + kb + a_kc) * 2;
                LDSM4(a[mt],   sAh + ra);
                LDSM4(al2[mt], sAl + ra);
            }

            uint32_t bh[4][4], bl[4][4];
#pragma unroll
            for (int p = 0; p < 4; p++) {
                uint32_t rb = ((noff + p * 16 + b_row) * STR + kb + b_kc) * 2;
                LDSM4(bh[p], sWh + rb);
                LDSM4(bl[p], sWl + rb);
            }

#pragma unroll
            for (int mt = 0; mt < 2; mt++)
#pragma unroll
                for (int nt = 0; nt < 8; nt++) {
                    MMA_BF16(acc[mt][nt], a[mt],   &bh[nt >> 1][(nt & 1) * 2]);
                    MMA_BF16(acc[mt][nt], a[mt],   &bl[nt >> 1][(nt & 1) * 2]);
                    MMA_BF16(acc[mt][nt], al2[mt], &bh[nt >> 1][(nt & 1) * 2]);
                }
        }

        __syncthreads();
        if (c + 2 < NCHUNK) load_chunk((c + 2) * 32, st);
    }

    // ---- epilogue: route to C0 (cols < 768) or C1 (cols >= 768) ----
    float* Cb = C0;
    int nb = n0;
    if (n0 >= CD) { Cb = C1; nb = n0 - CD; }

#pragma unroll
    for (int mt = 0; mt < 2; mt++) {
        int r0 = m0 + moff + mt * 16 + gid;
#pragma unroll
        for (int nt = 0; nt < 8; nt++) {
            int col = nb + noff + nt * 8 + qid * 2;
            float b0 = 0.f, b1 = 0.f;
            if (BIAS) { b0 = __ldg(bias + col); b1 = __ldg(bias + col + 1); }
            float2 v0 = make_float2(acc[mt][nt][0] + b0, acc[mt][nt][1] + b1);
            float2 v1 = make_float2(acc[mt][nt][2] + b0, acc[mt][nt][3] + b1);
            *(float2*)(Cb + (size_t)r0 * CD + col)       = v0;
            *(float2*)(Cb + (size_t)(r0 + 8) * CD + col) = v1;
        }
    }
}

// ---------------------------------------------------------------------------
// fp32 -> (bf16 hi, bf16 lo) split conversion
// ---------------------------------------------------------------------------
__global__ void cvt_pair(const float4* __restrict__ src,
                         __nv_bfloat162* __restrict__ hi,
                         __nv_bfloat162* __restrict__ lo, int n4)
{
    int i = blockIdx.x * blockDim.x + threadIdx.x;
    if (i >= n4) return;
    float4 v = src[i];
    __nv_bfloat16 h0 = __float2bfloat16(v.x), h1 = __float2bfloat16(v.y);
    __nv_bfloat16 h2 = __float2bfloat16(v.z), h3 = __float2bfloat16(v.w);
    __nv_bfloat16 l0 = __float2bfloat16(v.x - __bfloat162float(h0));
    __nv_bfloat16 l1 = __float2bfloat16(v.y - __bfloat162float(h1));
    __nv_bfloat16 l2 = __float2bfloat16(v.z - __bfloat162float(h2));
    __nv_bfloat16 l3 = __float2bfloat16(v.w - __bfloat162float(h3));
    hi[2 * i]     = __halves2bfloat162(h0, h1);
    hi[2 * i + 1] = __halves2bfloat162(h2, h3);
    lo[2 * i]     = __halves2bfloat162(l0, l1);
    lo[2 * i + 1] = __halves2bfloat162(l2, l3);
}

// ---------------------------------------------------------------------------
// 1/softplus(scale)
// ---------------------------------------------------------------------------
__global__ void rsoftplus_kernel(const float* __restrict__ scale, float* __restrict__ rsp)
{
    int c = blockIdx.x * blockDim.x + threadIdx.x;
    if (c < CD) {
        float s = scale[c];
        float sp = (s > 20.f) ? s : log1pf(expf(s));
        rsp[c] = 1.f / sp;
    }
}

// ---------------------------------------------------------------------------
// Focusing nonlinearity for k (in-place)
// ---------------------------------------------------------------------------
__global__ __launch_bounds__(256) void process_kernel(float* __restrict__ t,
                                                      const float* __restrict__ rsp)
{
    float* row = t + (size_t)blockIdx.x * CD;
    const int tid = threadIdx.x;

    float v[3];
    float s2 = 0.f, s6 = 0.f;
#pragma unroll
    for (int i = 0; i < 3; i++) {
        int c = tid + i * 256;
        float x = row[c];
        x = (x > 0.f ? x : 0.f) + EPSF;
        x = x * rsp[c];
        v[i] = x;
        float x2 = x * x;
        s2 += x2;
        s6 += x2 * x2 * x2;
    }
#pragma unroll
    for (int off = 16; off > 0; off >>= 1) {
        s2 += __shfl_xor_sync(0xffffffffu, s2, off);
        s6 += __shfl_xor_sync(0xffffffffu, s6, off);
    }
    __shared__ float sA[8], sB[8];
    int warp = tid >> 5, lane = tid & 31;
    if (lane == 0) { sA[warp] = s2; sB[warp] = s6; }
    __syncthreads();
    if (warp == 0) {
        float a = (lane < 8) ? sA[lane] : 0.f;
        float b = (lane < 8) ? sB[lane] : 0.f;
#pragma unroll
        for (int off = 4; off > 0; off >>= 1) {
            a += __shfl_xor_sync(0xffffffffu, a, off);
            b += __shfl_xor_sync(0xffffffffu, b, off);
        }
        if (lane == 0) { sA[0] = a; sB[0] = b; }
    }
    __syncthreads();
    float f = sqrtf(sA[0]) / sqrtf(sB[0]);
#pragma unroll
    for (int i = 0; i < 3; i++) {
        int c = tid + i * 256;
        row[c] = v[i] * v[i] * v[i] * f;
    }
}

// ---------------------------------------------------------------------------
// kv partial + reduce
// ---------------------------------------------------------------------------
__global__ __launch_bounds__(256) void kv_partial_kernel(const float* __restrict__ k,
                                                         const float* __restrict__ v,
                                                         float* __restrict__ kvp,
                                                         float* __restrict__ kmp)
{
    const int bh = blockIdx.x;
    const int b  = bh / HD;
    const int hh = bh % HD;
    const int n0 = blockIdx.y * (NM / KVSPLIT);
    const int t  = threadIdx.x;
    const int d1 = t >> 2;
    const int c0 = (t & 3) * 16;

    __shared__ float ks[DD], vs[DD];

    float acc[16];
#pragma unroll
    for (int j = 0; j < 16; j++) acc[j] = 0.f;
    float ksum = 0.f;

    for (int n = n0; n < n0 + NM / KVSPLIT; n++) {
        size_t base = ((size_t)n * BD + b) * CD + hh * DD;
        if (t < DD)           ks[t]      = k[base + t];
        else if (t < 2 * DD)  vs[t - DD] = v[base + t - DD];
        __syncthreads();
        float kd = ks[d1];
#pragma unroll
        for (int j = 0; j < 16; j++) acc[j] = fmaf(kd, vs[c0 + j], acc[j]);
        if (t < DD) ksum += ks[t];
        __syncthreads();
    }

    const float s = 1.f / (float)NM;
    float* outp = kvp + ((size_t)blockIdx.y * (BD * HD) + bh) * (DD * DD) + d1 * DD + c0;
#pragma unroll
    for (int j = 0; j < 16; j++) outp[j] = acc[j] * s;
    if (t < DD) kmp[((size_t)blockIdx.y * (BD * HD) + bh) * DD + t] = ksum * s;
}

__global__ void kv_reduce_kernel(const float* __restrict__ kvp, const float* __restrict__ kmp,
                                 float* __restrict__ kv, float* __restrict__ km)
{
    int idx = blockIdx.x * blockDim.x + threadIdx.x;
    const int NKV = BD * HD * DD * DD;
    const int NKM = BD * HD * DD;
    if (idx < NKV) {
        float s = 0.f;
#pragma unroll
        for (int p = 0; p < KVSPLIT; p++) s += kvp[(size_t)p * NKV + idx];
        kv[idx] = s;
    } else if (idx < NKV + NKM) {
        int i = idx - NKV;
        float s = 0.f;
#pragma unroll
        for (int p = 0; p < KVSPLIT; p++) s += kmp[(size_t)p * NKM + i];
        km[i] = s;
    }
}

// ---------------------------------------------------------------------------
// depthwise 5x5 conv (bias included)
// ---------------------------------------------------------------------------
__global__ __launch_bounds__(256) void dwconv_kernel(const float* __restrict__ v,
                                                     const float* __restrict__ w,
                                                     const float* __restrict__ bias,
                                                     float* __restrict__ dwc)
{
    __shared__ float ws[DD * 25];
    __shared__ float bs[DD];
    const int t = threadIdx.x;
    for (int i = t; i < DD * 25; i += 256) ws[i] = w[i];
    if (t < DD) bs[t] = bias[t];
    __syncthreads();

    size_t idx = (size_t)blockIdx.x * 256 + t;
    int c  = (int)(idx % CD);
    int rb = (int)(idx / CD);
    int b  = rb & 1;
    int n  = rb >> 1;
    int y   = n >> 8;
    int col = n & 255;
    int dd  = c & (DD - 1);

    float acc = bs[dd];
#pragma unroll
    for (int dy = -2; dy <= 2; dy++) {
        int y2 = y + dy;
        if (y2 < 0 || y2 >= GRID_H) continue;
#pragma unroll
        for (int dx = -2; dx <= 2; dx++) {
            int c2 = col + dx;
            if (c2 < 0 || c2 >= GRID_W) continue;
            int n2 = (y2 << 8) + c2;
            acc = fmaf(ws[dd * 25 + (dy + 2) * 5 + (dx + 2)],
                       v[((size_t)n2 * BD + b) * CD + c], acc);
        }
    }
    dwc[idx] = acc;
}

// ---------------------------------------------------------------------------
// FUSED: focusing(q) + attention matvec + dwc add + bf16 split write
// round-9 shell (16 rows/block, 2 rows/warp, 69KB, 2 CTAs/SM) with
// restructured matvec: one kv LDS.64 feeds BOTH rows (4 FMA per load).
// ---------------------------------------------------------------------------
#define AT_RS   0
#define AT_KMS  768
#define AT_KVS  832
#define AT_QS   4928
#define AT_QSTR 776
#define ATTN_SMEM ((AT_QS + 16 * AT_QSTR) * 4)   // 69376 bytes

__global__ __launch_bounds__(256, 2)
void attn_fused(const float* __restrict__ q, const float* __restrict__ rsp,
                const float* __restrict__ kv, const float* __restrict__ km,
                const float* __restrict__ dwc,
                __nv_bfloat162* __restrict__ hi, __nv_bfloat162* __restrict__ lo)
{
    extern __shared__ float sm[];
    float* rs  = sm + AT_RS;
    float* kms = sm + AT_KMS;
    float* kvs = sm + AT_KVS;
    float* qs  = sm + AT_QS;

    const int tid  = threadIdx.x;
    const int wid  = tid >> 5;
    const int lane = tid & 31;
    const int b    = blockIdx.y;
    const int n0   = blockIdx.x * 16;

    if (tid < 192) ((float4*)rs)[tid] = ((const float4*)rsp)[tid];

#pragma unroll
    for (int i = 0; i < 12; i++) {
        int idx = tid + i * 256;
        int r = idx / 192, j = idx % 192;
        float4 vq = *(const float4*)(q + ((size_t)(n0 + r) * BD + b) * CD + j * 4);
        *(float4*)(qs + r * AT_QSTR + j * 4) = vq;
    }
    __syncthreads();

#pragma unroll
    for (int rr = 0; rr < 2; rr++) {
        const int row = wid * 2 + rr;
        float* qr = qs + row * AT_QSTR;
        float t[24];
        float s2 = 0.f, s6 = 0.f;
#pragma unroll
        for (int jj = 0; jj < 12; jj++) {
            int c = jj * 64 + lane * 2;
            float2 xv = *(float2*)(qr + c);
            float2 rv = *(float2*)(rs + c);
            float x0 = ((xv.x > 0.f ? xv.x : 0.f) + EPSF) * rv.x;
            float x1 = ((xv.y > 0.f ? xv.y : 0.f) + EPSF) * rv.y;
            t[jj * 2]     = x0;
            t[jj * 2 + 1] = x1;
            float p0 = x0 * x0, p1 = x1 * x1;
            s2 += p0 + p1;
            s6 += p0 * p0 * p0 + p1 * p1 * p1;
        }
#pragma unroll
        for (int off = 16; off > 0; off >>= 1) {
            s2 += __shfl_xor_sync(0xffffffffu, s2, off);
            s6 += __shfl_xor_sync(0xffffffffu, s6, off);
        }
        float f = sqrtf(s2) / sqrtf(s6);
#pragma unroll
        for (int jj = 0; jj < 12; jj++) {
            int c = jj * 64 + lane * 2;
            float x0 = t[jj * 2], x1 = t[jj * 2 + 1];
            float2 o = make_float2(x0 * x0 * x0 * f, x1 * x1 * x1 * f);
            *(float2*)(qr + c) = o;
        }
    }
    __syncthreads();

    for (int hh = 0; hh < HD; hh++) {
        const int bh = b * HD + hh;
        const float4* kvg = (const float4*)(kv + (size_t)bh * DD * DD);
#pragma unroll
        for (int i = 0; i < 4; i++)
            ((float4*)kvs)[tid + i * 256] = kvg[tid + i * 256];
        if (tid < 16) ((float4*)kms)[tid] = ((const float4*)(km + (size_t)bh * DD))[tid];
        __syncthreads();

        const float* qh0 = qs + (wid * 2 + 0) * AT_QSTR + hh * DD;
        const float* qh1 = qs + (wid * 2 + 1) * AT_QSTR + hh * DD;

        // z for both rows
        float z0, z1;
        {
            float2 k2 = *(float2*)(kms + lane * 2);
            float2 qa = *(float2*)(qh0 + lane * 2);
            float2 qb = *(float2*)(qh1 + lane * 2);
            float p0 = qa.x * k2.x + qa.y * k2.y;
            float p1 = qb.x * k2.x + qb.y * k2.y;
#pragma unroll
            for (int off = 16; off > 0; off >>= 1) {
                p0 += __shfl_xor_sync(0xffffffffu, p0, off);
                p1 += __shfl_xor_sync(0xffffffffu, p1, off);
            }
            z0 = 1.f / (p0 + EPSF);
            z1 = 1.f / (p1 + EPSF);
        }

        // matvec: one kv load serves both rows
        float ax0 = 0.f, ay0 = 0.f, ax1 = 0.f, ay1 = 0.f;
#pragma unroll 8
        for (int dd = 0; dd < DD; dd++) {
            float2 kvv = *(float2*)(kvs + dd * DD + lane * 2);
            float q0 = qh0[dd];
            float q1 = qh1[dd];
            ax0 = fmaf(q0, kvv.x, ax0);
            ay0 = fmaf(q0, kvv.y, ay0);
            ax1 = fmaf(q1, kvv.x, ax1);
            ay1 = fmaf(q1, kvv.y, ay1);
        }

#pragma unroll
        for (int rr = 0; rr < 2; rr++) {
            const int n = n0 + wid * 2 + rr;
            float ax = (rr == 0 ? ax0 : ax1) * (rr == 0 ? z0 : z1);
            float ay = (rr == 0 ? ay0 : ay1) * (rr == 0 ? z0 : z1);

            int dn = n & (NM - 1);
            float2 dw = *(const float2*)(dwc + ((size_t)dn * BD + b) * CD + hh * DD + lane * 2);
            ax += dw.x; ay += dw.y;

            __nv_bfloat16 h0 = __float2bfloat16(ax);
            __nv_bfloat16 h1 = __float2bfloat16(ay);
            __nv_bfloat16 l0 = __float2bfloat16(ax - __bfloat162float(h0));
            __nv_bfloat16 l1 = __float2bfloat16(ay - __bfloat162float(h1));
            size_t o = (((size_t)n * BD + b) * CD + hh * DD + lane * 2) >> 1;
            hi[o] = __halves2bfloat162(h0, h1);
            lo[o] = __halves2bfloat162(l0, l1);
        }
        __syncthreads();
    }
}

// ---------------------------------------------------------------------------
// kernel_launch — two-branch graph with rebalanced chains:
//   main: x-cvt, wq-cvt, Q-GEMM, wproj-cvt, dwconv (after evV)
//   s2:   mem-cvt, wk/wv-cvt, KV-GEMM (evV), process_k, kv partial+reduce (evJoin)
// ---------------------------------------------------------------------------
extern "C" void kernel_launch(void* const* d_in, const int* in_sizes, int n_in,
                              void* d_out, int out_size)
{
    const float* x      = (const float*)d_in[0];
    const float* memory = (const float*)d_in[1];
    const float* w_q    = (const float*)d_in[2];
    const float* w_k    = (const float*)d_in[3];
    const float* w_v    = (const float*)d_in[4];
    const float* w_proj = (const float*)d_in[5];
    const float* b_proj = (const float*)d_in[6];
    const float* dwc_w  = (const float*)d_in[7];
    const float* dwc_b  = (const float*)d_in[8];
    const float* scale  = (const float*)d_in[9];
    float* out = (float*)d_out;

    float *p_q, *p_k, *p_v, *p_dwc, *p_kvp, *p_kmp, *p_kv, *p_km, *p_rsp;
    __nv_bfloat16 *p_ah, *p_al, *p_bh, *p_bl, *p_wh, *p_wl;
    cudaGetSymbolAddress((void**)&p_q,   g_q);
    cudaGetSymbolAddress((void**)&p_k,   g_k);
    cudaGetSymbolAddress((void**)&p_v,   g_v);
    cudaGetSymbolAddress((void**)&p_dwc, g_dwc);
    cudaGetSymbolAddress((void**)&p_kvp, g_kvp);
    cudaGetSymbolAddress((void**)&p_kmp, g_kmp);
    cudaGetSymbolAddress((void**)&p_kv,  g_kv);
    cudaGetSymbolAddress((void**)&p_km,  g_km);
    cudaGetSymbolAddress((void**)&p_rsp, g_rsp);
    cudaGetSymbolAddress((void**)&p_ah,  g_ah);
    cudaGetSymbolAddress((void**)&p_al,  g_al);
    cudaGetSymbolAddress((void**)&p_bh,  g_bh);
    cudaGetSymbolAddress((void**)&p_bl,  g_bl);
    cudaGetSymbolAddress((void**)&p_wh,  g_wh);
    cudaGetSymbolAddress((void**)&p_wl,  g_wl);

    cudaFuncSetAttribute(gemm_mma<false>, cudaFuncAttributeMaxDynamicSharedMemorySize, GEMM_SMEM);
    cudaFuncSetAttribute(gemm_mma<true>,  cudaFuncAttributeMaxDynamicSharedMemorySize, GEMM_SMEM);
    cudaFuncSetAttribute(attn_fused,      cudaFuncAttributeMaxDynamicSharedMemorySize, ATTN_SMEM);

    // One-time host-side handles (no device memory involved).
    static cudaStream_t s2 = nullptr;
    static cudaEvent_t evFork = nullptr, evV = nullptr, evJoin = nullptr;
    if (s2 == nullptr) {
        cudaStreamCreateWithFlags(&s2, cudaStreamNonBlocking);
        cudaEventCreateWithFlags(&evFork, cudaEventDisableTiming);
        cudaEventCreateWithFlags(&evV,    cudaEventDisableTiming);
        cudaEventCreateWithFlags(&evJoin, cudaEventDisableTiming);
    }

    const int WN4 = CD * CD / 4;
    const int WCVT_GRID = (WN4 + 255) / 256;

    // ---- prologue + fork ----
    rsoftplus_kernel<<<3, 256>>>(scale, p_rsp);
    cudaEventRecord(evFork, 0);
    cudaStreamWaitEvent(s2, evFork, 0);

    // ---- s2: KV chain ----
    cvt_pair<<<(MK * CD / 4 + 255) / 256, 256, 0, s2>>>((const float4*)memory,
        (__nv_bfloat162*)p_bh, (__nv_bfloat162*)p_bl, MK * CD / 4);
    cvt_pair<<<WCVT_GRID, 256, 0, s2>>>((const float4*)w_k,
        (__nv_bfloat162*)(p_wh + 1 * CD * CD), (__nv_bfloat162*)(p_wl + 1 * CD * CD), WN4);
    cvt_pair<<<WCVT_GRID, 256, 0, s2>>>((const float4*)w_v,
        (__nv_bfloat162*)(p_wh + 2 * CD * CD), (__nv_bfloat162*)(p_wl + 2 * CD * CD), WN4);
    gemm_mma<false><<<dim3(2 * CD / 128, MK / 128), 256, GEMM_SMEM, s2>>>(
        p_bh, p_bl, p_wh + 1 * CD * CD, p_wl + 1 * CD * CD, p_k, p_v, nullptr);
    cudaEventRecord(evV, s2);
    process_kernel<<<MK, 256, 0, s2>>>(p_k, p_rsp);
    kv_partial_kernel<<<dim3(BD * HD, KVSPLIT), 256, 0, s2>>>(p_k, p_v, p_kvp, p_kmp);
    {
        int tot = BD * HD * DD * DD + BD * HD * DD;
        kv_reduce_kernel<<<(tot + 255) / 256, 256, 0, s2>>>(p_kvp, p_kmp, p_kv, p_km);
    }
    cudaEventRecord(evJoin, s2);

    // ---- main: Q chain (concurrent with s2) ----
    cvt_pair<<<(MQ * CD / 4 + 255) / 256, 256>>>((const float4*)x,
        (__nv_bfloat162*)p_ah, (__nv_bfloat162*)p_al, MQ * CD / 4);
    cvt_pair<<<WCVT_GRID, 256>>>((const float4*)w_q,
        (__nv_bfloat162*)(p_wh + 0 * CD * CD), (__nv_bfloat162*)(p_wl + 0 * CD * CD), WN4);
    gemm_mma<false><<<dim3(CD / 128, MQ / 128), 256, GEMM_SMEM>>>(
        p_ah, p_al, p_wh + 0 * CD * CD, p_wl + 0 * CD * CD, p_q, p_q, nullptr);
    cvt_pair<<<WCVT_GRID, 256>>>((const float4*)w_proj,
        (__nv_bfloat162*)(p_wh + 3 * CD * CD), (__nv_bfloat162*)(p_wl + 3 * CD * CD), WN4);

    // dwconv on main once v is ready (overlaps s2's process_k/kv_partial)
    cudaStreamWaitEvent(0, evV, 0);
    {
        size_t tot = (size_t)NM * BD * CD;
        dwconv_kernel<<<(unsigned)(tot / 256), 256>>>(p_v, dwc_w, dwc_b, p_dwc);
    }

    // ---- join, then attn + final projection ----
    cudaStreamWaitEvent(0, evJoin, 0);

    attn_fused<<<dim3(NX / 16, BD), 256, ATTN_SMEM>>>(
        p_q, p_rsp, p_kv, p_km, p_dwc,
        (__nv_bfloat162*)p_ah, (__nv_bfloat162*)p_al);

    gemm_mma<true><<<dim3(CD / 128, MQ / 128), 256, GEMM_SMEM>>>(
        p_ah, p_al, p_wh + 3 * CD * CD, p_wl + 3 * CD * CD, out, out, b_proj);
}